// round 16
// baseline (speedup 1.0000x reference)
#include <cuda_runtime.h>
#include <cuda_fp16.h>
#include <math.h>
#include <stdint.h>

#define SQC 0.70710678118f

// ---------------- device scratch ----------------
__device__ float g_prev[1312];
__device__ float g_cond[48000];
__device__ float g_ciAll[4 * 9 * 2 * 800 * 128];
__device__ float g_bp[4 * 8 * 384];
__device__ __half g_WpH[4 * 8 * 384 * 256];
__device__ __half g_WpL[4 * 8 * 384 * 256];
__device__ __half g_hA[800 * 256 * 128];
__device__ __half g_hB[800 * 256 * 128];

// ---------------- helpers ----------------
__device__ __forceinline__ uint32_t smem_u32(const void* p) {
    uint32_t a;
    asm("{ .reg .u64 t; cvta.to.shared.u64 t, %1; cvt.u32.u64 %0, t; }" : "=r"(a) : "l"(p));
    return a;
}
__device__ __forceinline__ void cpa16(uint32_t dst, const void* src) {
    asm volatile("cp.async.cg.shared.global [%0], [%1], 16;"
                 :: "r"(dst), "l"((unsigned long long)__cvta_generic_to_global(src)));
}
__device__ __forceinline__ void mma_f16(float* c, const uint32_t* a, const uint32_t* b) {
    asm volatile("mma.sync.aligned.m16n8k16.row.col.f32.f16.f16.f32 "
                 "{%0,%1,%2,%3}, {%4,%5,%6,%7}, {%8,%9}, {%0,%1,%2,%3};"
                 : "+f"(c[0]), "+f"(c[1]), "+f"(c[2]), "+f"(c[3])
                 : "r"(a[0]), "r"(a[1]), "r"(a[2]), "r"(a[3]), "r"(b[0]), "r"(b[1]));
}
#define LDM4(r0, r1, r2, r3, addr) \
    asm volatile("ldmatrix.sync.aligned.m8n8.x4.shared.b16 {%0,%1,%2,%3}, [%4];" \
                 : "=r"(r0), "=r"(r1), "=r"(r2), "=r"(r3) : "r"(addr))
#define LDM2(r0, r1, addr) \
    asm volatile("ldmatrix.sync.aligned.m8n8.x2.shared.b16 {%0,%1}, [%2];" \
                 : "=r"(r0), "=r"(r1) : "r"(addr))

__device__ __forceinline__ float fsig(float x) { return __fdividef(1.f, 1.f + __expf(-x)); }
__device__ __forceinline__ float fth(float x)  { return 2.f * fsig(2.f * x) - 1.f; }

// ---------------- prep 0: init + cond ----------------
__global__ void k_prep0(const float* __restrict__ sig, float* __restrict__ out,
                        const float* __restrict__ mgc, const float* __restrict__ cw,
                        const float* __restrict__ cb) {
    int b = blockIdx.x, tid = threadIdx.x;
    if (b == 188) {
        for (int i = tid; i < 1312; i += 256) g_prev[i] = sig[i];
        for (int i = tid; i < 800; i += 256) out[i] = sig[512 + i];
        return;
    }
    int id = b * 256 + tid;
    if (id >= 48000) return;
    int t = id / 12000, w = id % 12000;
    const float* wr = cw + w * 60;
    const float* mg = mgc + t * 60;
    float s = cb[w];
#pragma unroll
    for (int k = 0; k < 60; k++) s += mg[k] * wr[k];
    g_cond[(t * 200 + w / 60) * 60 + (w % 60)] = tanhf(s);
}

// ---------------- prep 1: ciall + wprep (fused) ----------------
__global__ void k_prep1(const float* __restrict__ clw, const float* __restrict__ clb,
                        const float* __restrict__ wL, const float* __restrict__ bL) {
    int b = blockIdx.x, tid = threadIdx.x;
    if (b < 1800) {
        __shared__ float cs[32][60];
        int wg = b / 25, nt = b % 25;
        for (int i = tid; i < 32 * 60; i += 256)
            cs[i / 60][i % 60] = g_cond[(nt * 32 + i / 60) * 60 + (i % 60)];
        __syncthreads();
        int f = tid & 127, nh = tid >> 7;
        float wr[60];
        const float* wsrc = clw + (wg * 128 + f) * 60;
#pragma unroll
        for (int k = 0; k < 60; k++) wr[k] = wsrc[k];
        float bia = clb[wg * 128 + f];
        for (int nn = nh * 16; nn < nh * 16 + 16; nn++) {
            float s = bia;
#pragma unroll
            for (int k = 0; k < 60; k++) s += wr[k] * cs[nn][k];
            g_ciAll[(wg * 800 + nt * 32 + nn) * 128 + f] = s;
        }
        return;
    }
    int idx = (b - 1800) * 256 + tid;
    const int total = 4 * 8 * 384 * 256;
    if (idx < total) {
        int k  = idx & 255;
        int r  = (idx >> 8) % 384;
        int bl = idx / (384 * 256);
        int f = r / 3, t = r % 3, kk = k >> 7, c = k & 127;
        float w = wL[(((bl * 3 + t) * 128 + f) * 128 + c) * 2 + kk];
        __half hi = __float2half_rn(w);
        g_WpH[idx] = hi;
        g_WpL[idx] = __float2half_rn(w - __half2float(hi));
    }
    if (idx < 4 * 8 * 384) {
        int r = idx % 384, bl = idx / 384;
        g_bp[idx] = bL[(bl * 3 + (r % 3)) * 128 + (r / 3)];
    }
}

// ---------------- layer 0 (Cin=1), 8 outputs/thread, 16B stores ----------------
__global__ void k_layer0(const float* __restrict__ w0, const float* __restrict__ b0, int blk) {
    int gid = blockIdx.x * 256 + threadIdx.x;     // 800*256*16 quads
    if (gid >= 800 * 256 * 16) return;
    int m = gid >> 4, q = gid & 15;
    int n = m >> 8, j = m & 255;
    const float* ci = g_ciAll + (size_t)(blk * 9 * 2) * 102400;
    const float* cg = ci + 102400;
    float a = g_prev[n + 2 * j], b = g_prev[n + 2 * j + 1];
    __half2 h2[4];
#pragma unroll
    for (int p = 0; p < 4; p++) {
        float x2[2];
#pragma unroll
        for (int e = 0; e < 2; e++) {
            int f = q * 8 + p * 2 + e;
            float o0 = a * w0[f * 2]         + b * w0[f * 2 + 1]         + b0[f];
            float o1 = a * w0[(128 + f) * 2] + b * w0[(128 + f) * 2 + 1] + b0[128 + f];
            float o2 = a * w0[(256 + f) * 2] + b * w0[(256 + f) * 2 + 1] + b0[256 + f];
            float it = fth(o0 + ci[n * 128 + f]);
            float gt = fsig(o1 + cg[n * 128 + f]);
            x2[e] = (it * gt + o2) * SQC;
        }
        h2[p] = __floats2half2_rn(x2[0], x2[1]);
    }
    *((uint4*)g_hA + gid) = *(uint4*)h2;
}

// ------------- 1-term layers (l1-l7): BK=64, 4 chunks, 2-slot ring -------
// CTA BM=16*MI x 192; 8 warps, rN=8 (warp-private 24 gates). No mainloop barriers.
#define B64_BSTG (192 * 144)        /* 27648 */

template<int MI>
__global__ void __launch_bounds__(256, 2)
k_layer_b64(int dir, int wtile, int lidx, int M, int logL) {
    constexpr int BM = 16 * MI;
    constexpr int ASZ = BM * 528;
    constexpr int CPITCH = 200;
    extern __shared__ __align__(16) char sm[];
    float* Cs = (float*)sm;
    uint32_t smb = smem_u32(sm);

    const int tid  = threadIdx.x;
    const int lane = tid & 31, wid = tid >> 5;
    const int gid  = lane >> 2, tig = lane & 3;

    const int m0 = blockIdx.x * BM;
    const int ntile = blockIdx.y;
    const long r0 = (long)wtile * 384 + ntile * 192;

    const __half* A = dir ? g_hB : g_hA;
    __half* O       = dir ? g_hA : g_hB;

    float acc[MI][3][4];
#pragma unroll
    for (int a = 0; a < MI; a++)
#pragma unroll
        for (int b = 0; b < 3; b++)
#pragma unroll
            for (int c = 0; c < 4; c++) acc[a][b][c] = 0.f;

    // warp-private B streaming bases (6 cpa16/chunk, strided)
    const __half* srcB = g_WpH + (r0 + wid * 24 + (lane >> 3)) * 256 + (lane & 7) * 8;
    const uint32_t dstB = smb + ASZ + (wid * 24 + (lane >> 3)) * 144 + (lane & 7) * 16;

    // ---- prologue group 0: full A tile (cooperative) ----
#pragma unroll
    for (int i = 0; i < 2 * MI; i++) {
        int idx = tid + i * 256;
        int row = idx >> 5, seg = idx & 31;
        cpa16(smb + row * 528 + seg * 16,
              A + (size_t)(m0 + row) * 256 + seg * 8);
    }
    asm volatile("cp.async.commit_group;");

    // ---- prologue groups 1,2: B chunks 0,1 -> slots 0,1 ----
#pragma unroll
    for (int c = 0; c < 2; c++) {
#pragma unroll
        for (int i = 0; i < 6; i++)
            cpa16(dstB + c * B64_BSTG + i * 576, srcB + i * 1024 + c * 64);
        asm volatile("cp.async.commit_group;");
    }

    asm volatile("cp.async.wait_group 2;");
    __syncthreads();

    const int aRow = lane & 15;
    const int aHalf = (lane >> 4) * 16;
    const uint32_t bAdr  = smb + ASZ + (wid * 24 + ((lane >> 4) << 3) + (lane & 7)) * 144
                         + ((lane >> 3) & 1) * 16;
    const uint32_t bAdr2 = smb + ASZ + (wid * 24 + 16 + (lane & 7)) * 144
                         + ((lane >> 3) & 1) * 16;

    for (int ks = 0; ks < 4; ks++) {
        if (ks < 3) asm volatile("cp.async.wait_group 1;");
        else        asm volatile("cp.async.wait_group 0;");
        uint32_t Bst = (ks & 1) * B64_BSTG;

        uint32_t bf[4][3][2];
#pragma unroll
        for (int kf = 0; kf < 4; kf++) {
            LDM4(bf[kf][0][0], bf[kf][0][1], bf[kf][1][0], bf[kf][1][1],
                 bAdr + Bst + kf * 32);
            LDM2(bf[kf][2][0], bf[kf][2][1], bAdr2 + Bst + kf * 32);
        }

        if (ks < 2) {
            int c = ks + 2;
            uint32_t db = dstB + (ks & 1) * B64_BSTG;
#pragma unroll
            for (int i = 0; i < 6; i++)
                cpa16(db + i * 576, srcB + i * 1024 + c * 64);
            asm volatile("cp.async.commit_group;");
        }

#pragma unroll
        for (int kf = 0; kf < 4; kf++) {
            uint32_t af[MI][4];
#pragma unroll
            for (int mi = 0; mi < MI; mi++)
                LDM4(af[mi][0], af[mi][1], af[mi][2], af[mi][3],
                     smb + (mi * 16 + aRow) * 528 + ks * 128 + kf * 32 + aHalf);
#pragma unroll
            for (int mi = 0; mi < MI; mi++)
#pragma unroll
                for (int ni = 0; ni < 3; ni++)
                    mma_f16(acc[mi][ni], af[mi], bf[kf][ni]);
        }
    }
    __syncthreads();

    // ---- epilogue: accums -> smem -> fused gating -> fp16 out ----
#pragma unroll
    for (int mi = 0; mi < MI; mi++)
#pragma unroll
        for (int ni = 0; ni < 3; ni++) {
            int ml = mi * 16 + gid;
            int rl = wid * 24 + ni * 8 + tig * 2;
            Cs[ml * CPITCH + rl]           = acc[mi][ni][0];
            Cs[ml * CPITCH + rl + 1]       = acc[mi][ni][1];
            Cs[(ml + 8) * CPITCH + rl]     = acc[mi][ni][2];
            Cs[(ml + 8) * CPITCH + rl + 1] = acc[mi][ni][3];
        }
    __syncthreads();

    const int fl = tid & 63;
    const int fg = ntile * 64 + fl;
    const float* bpp = g_bp + wtile * 384 + ntile * 192;
    float b0 = bpp[fl * 3], b1 = bpp[fl * 3 + 1], b2 = bpp[fl * 3 + 2];
    const float* ci = g_ciAll + (size_t)lidx * 2 * 102400;
    const float* cg = ci + 102400;
#pragma unroll
    for (int i = 0; i < BM / 4; i++) {
        int ml = (tid >> 6) + i * 4;
        int m = m0 + ml;
        if (m < M) {
            int n = m >> logL;
            float o0 = Cs[ml * CPITCH + fl * 3]     + b0 + ci[(size_t)n * 128 + fg];
            float o1 = Cs[ml * CPITCH + fl * 3 + 1] + b1 + cg[(size_t)n * 128 + fg];
            float o2 = Cs[ml * CPITCH + fl * 3 + 2] + b2;
            float x = (fth(o0) * fsig(o1) + o2) * SQC;
            O[(size_t)m * 128 + fg] = __float2half_rn(x);
        }
    }
}

// ------------- l8 (2-term): R13 structure, BK=32, 2-buffer ----
template<int MI, int TERMS>
__global__ void __launch_bounds__(256, 2)
k_layer_f(int dir, int wtile, int lidx, int M, int logL) {
    constexpr int BM = 16 * MI;
    constexpr int ASZ = BM * 528;
    constexpr int BROW = 192 * TERMS;
    constexpr int BSTG = BROW * 80;
    constexpr int NR = 3 * TERMS;
    constexpr int CPITCH = 200;

    extern __shared__ __align__(16) char sm[];
    float* Cs = (float*)sm;
    uint32_t smb = smem_u32(sm);

    const int tid  = threadIdx.x;
    const int lane = tid & 31, wid = tid >> 5;
    const int gid  = lane >> 2, tig = lane & 3;

    const int m0 = blockIdx.x * BM;
    const int ntile = blockIdx.y;
    const long r0 = (long)wtile * 384 + ntile * 192;

    const __half* A = dir ? g_hB : g_hA;
    __half* O       = dir ? g_hA : g_hB;

    float acc[MI][3][4];
#pragma unroll
    for (int a = 0; a < MI; a++)
#pragma unroll
        for (int b = 0; b < 3; b++)
#pragma unroll
            for (int c = 0; c < 4; c++) acc[a][b][c] = 0.f;

    const __half* srcp[NR];
    uint32_t dsto[NR];
#pragma unroll
    for (int i = 0; i < NR; i++) {
        int idx = lane + i * 32;
        int rl = idx >> 2, seg = idx & 3;
        int prec = (TERMS == 2) ? (rl >= 24) : 0;
        int gl = rl - prec * 24;
        srcp[i] = (prec ? g_WpL : g_WpH) + (r0 + wid * 24 + gl) * 256 + seg * 8;
        dsto[i] = (uint32_t)((prec * 192 + wid * 24 + gl) * 80 + seg * 16);
    }

#pragma unroll
    for (int i = 0; i < BM * 32 / 256; i++) {
        int idx = tid + i * 256;
        int row = idx >> 5, seg = idx & 31;
        cpa16(smb + row * 528 + seg * 16,
              A + (size_t)(m0 + row) * 256 + seg * 8);
    }
    asm volatile("cp.async.commit_group;");

#pragma unroll
    for (int c = 0; c < 2; c++) {
#pragma unroll
        for (int i = 0; i < NR; i++)
            cpa16(smb + ASZ + c * BSTG + dsto[i], srcp[i] + c * 32);
        asm volatile("cp.async.commit_group;");
    }

    asm volatile("cp.async.wait_group 2;");
    __syncthreads();

    const int aRow = lane & 15;
    const int aHalf = (lane >> 4) * 16;
    const int bRow = wid * 24 + ((lane >> 4) << 3) + (lane & 7);
    const int bRow2 = wid * 24 + 16 + (lane & 7);
    const int bByt = ((lane >> 3) & 1) * 16;

    for (int ks = 0; ks < 8; ks++) {
        if (ks < 7) asm volatile("cp.async.wait_group 1;");
        else        asm volatile("cp.async.wait_group 0;");
        uint32_t Bst = smb + ASZ + (ks & 1) * BSTG;
#pragma unroll
        for (int kf = 0; kf < 2; kf++) {
            uint32_t af[MI][4];
#pragma unroll
            for (int mi = 0; mi < MI; mi++)
                LDM4(af[mi][0], af[mi][1], af[mi][2], af[mi][3],
                     smb + (mi * 16 + aRow) * 528 + ks * 64 + kf * 32 + aHalf);
            uint32_t bf[TERMS][3][2];
#pragma unroll
            for (int prec = 0; prec < TERMS; prec++) {
                LDM4(bf[prec][0][0], bf[prec][0][1], bf[prec][1][0], bf[prec][1][1],
                     Bst + (prec * 192 + bRow) * 80 + bByt + kf * 32);
                LDM2(bf[prec][2][0], bf[prec][2][1],
                     Bst + (prec * 192 + bRow2) * 80 + bByt + kf * 32);
            }
#pragma unroll
            for (int mi = 0; mi < MI; mi++)
#pragma unroll
                for (int ni = 0; ni < 3; ni++) {
#pragma unroll
                    for (int prec = 0; prec < TERMS; prec++)
                        mma_f16(acc[mi][ni], af[mi], bf[prec][ni]);
                }
        }
        if (ks < 6) {
            uint32_t dbase = smb + ASZ + (ks & 1) * BSTG;
#pragma unroll
            for (int i = 0; i < NR; i++)
                cpa16(dbase + dsto[i], srcp[i] + (ks + 2) * 32);
            asm volatile("cp.async.commit_group;");
        }
    }
    __syncthreads();

#pragma unroll
    for (int mi = 0; mi < MI; mi++)
#pragma unroll
        for (int ni = 0; ni < 3; ni++) {
            int ml = mi * 16 + gid;
            int rl = wid * 24 + ni * 8 + tig * 2;
            Cs[ml * CPITCH + rl]           = acc[mi][ni][0];
            Cs[ml * CPITCH + rl + 1]       = acc[mi][ni][1];
            Cs[(ml + 8) * CPITCH + rl]     = acc[mi][ni][2];
            Cs[(ml + 8) * CPITCH + rl + 1] = acc[mi][ni][3];
        }
    __syncthreads();

    const int fl = tid & 63;
    const int fg = ntile * 64 + fl;
    const float* bpp = g_bp + wtile * 384 + ntile * 192;
    float b0 = bpp[fl * 3], b1 = bpp[fl * 3 + 1], b2 = bpp[fl * 3 + 2];
    const float* ci = g_ciAll + (size_t)lidx * 2 * 102400;
    const float* cg = ci + 102400;
#pragma unroll
    for (int i = 0; i < BM / 4; i++) {
        int ml = (tid >> 6) + i * 4;
        int m = m0 + ml;
        if (m < M) {
            int n = m >> logL;
            float o0 = Cs[ml * CPITCH + fl * 3]     + b0 + ci[(size_t)n * 128 + fg];
            float o1 = Cs[ml * CPITCH + fl * 3 + 1] + b1 + cg[(size_t)n * 128 + fg];
            float o2 = Cs[ml * CPITCH + fl * 3 + 2] + b2;
            float x = (fth(o0) * fsig(o1) + o2) * SQC;
            O[(size_t)m * 128 + fg] = __float2half_rn(x);
        }
    }
}

// ---------------- heads ----------------
__global__ void k_head(const float* __restrict__ pw, const float* __restrict__ pb,
                       const float* __restrict__ mw, const float* __restrict__ mb,
                       const float* __restrict__ sw, const float* __restrict__ sb,
                       const float* __restrict__ eps, float* __restrict__ out, int blk) {
    __shared__ float sm_[256], ss_[256];
    int n = blockIdx.x, o = threadIdx.x;
    const __half* h = g_hA + n * 128;
    const float* w = pw + o * 128;
    float s = pb[o];
#pragma unroll
    for (int k = 0; k < 128; k++) s += __half2float(h[k]) * w[k];
    s = fmaxf(s, 0.f);
    sm_[o] = s * mw[o];
    ss_[o] = s * sw[o];
    __syncthreads();
    for (int st = 128; st > 0; st >>= 1) {
        if (o < st) { sm_[o] += sm_[o + st]; ss_[o] += ss_[o + st]; }
        __syncthreads();
    }
    if (o == 0) {
        float mean = sm_[0] + mb[0];
        float logv = ss_[0] + sb[0];
        float nx = eps[n] * expf(0.5f * logv) + mean;
        out[800 + n]  = mean;
        out[1600 + n] = logv;
        if (n >= 288) out[2400 + blk * 512 + (n - 288)] = nx;
        g_prev[512 + n] = nx;
    }
}

// ---------------- launcher ----------------
extern "C" void kernel_launch(void* const* d_in, const int* in_sizes, int n_in,
                              void* d_out, int out_size) {
    const float* mgc       = (const float*)d_in[0];
    const float* signal    = (const float*)d_in[1];
    const float* cond_w    = (const float*)d_in[2];
    const float* cond_b    = (const float*)d_in[3];
    const float* conv0_w   = (const float*)d_in[4];
    const float* conv0_b   = (const float*)d_in[5];
    const float* convL_w   = (const float*)d_in[6];
    const float* convL_b   = (const float*)d_in[7];
    const float* condlin_w = (const float*)d_in[8];
    const float* condlin_b = (const float*)d_in[9];
    const float* pre_w     = (const float*)d_in[10];
    const float* pre_b     = (const float*)d_in[11];
    const float* mean_w    = (const float*)d_in[12];
    const float* mean_b    = (const float*)d_in[13];
    const float* std_w     = (const float*)d_in[14];
    const float* std_b     = (const float*)d_in[15];
    const float* eps       = (const float*)d_in[16];
    float* out = (float*)d_out;

    const int SMB4 = 64 * 528 + 2 * B64_BSTG;   // 89088
    const int SMB2 = 32 * 528 + 2 * B64_BSTG;   // 72192
    const int SMB1 = 16 * 528 + 2 * B64_BSTG;   // 63744
    const int SM12 = 16 * 528 + 2 * 384 * 80;   // 69888

    static bool attrSet = false;
    if (!attrSet) {
        cudaFuncSetAttribute((const void*)k_layer_b64<4>, cudaFuncAttributeMaxDynamicSharedMemorySize, SMB4);
        cudaFuncSetAttribute((const void*)k_layer_b64<2>, cudaFuncAttributeMaxDynamicSharedMemorySize, SMB2);
        cudaFuncSetAttribute((const void*)k_layer_b64<1>, cudaFuncAttributeMaxDynamicSharedMemorySize, SMB1);
        cudaFuncSetAttribute((const void*)k_layer_f<1, 2>, cudaFuncAttributeMaxDynamicSharedMemorySize, SM12);
        attrSet = true;
    }

    k_prep0<<<189, 256>>>(signal, out, mgc, cond_w, cond_b);
    k_prep1<<<1800 + 12288, 256>>>(condlin_w, condlin_b, convL_w, convL_b);

    for (int blk = 0; blk < 4; blk++) {
        k_layer0<<<12800, 256>>>(conv0_w + blk * 768, conv0_b + blk * 384, blk);
        for (int l = 1; l <= 8; l++) {
            int logL = 8 - l;
            int M = 800 << logL;
            int dir = (l & 1) ? 0 : 1;
            int wt = blk * 8 + l - 1, li = blk * 9 + l;
            if (M >= 12800) {
                k_layer_b64<4><<<dim3(M / 64, 2), 256, SMB4>>>(dir, wt, li, M, logL);
            } else if (M >= 3200) {
                k_layer_b64<2><<<dim3(M / 32, 2), 256, SMB2>>>(dir, wt, li, M, logL);
            } else if (M >= 1600) {
                k_layer_b64<1><<<dim3(M / 16, 2), 256, SMB1>>>(dir, wt, li, M, logL);
            } else {
                k_layer_f<1, 2><<<dim3(M / 16, 2), 256, SM12>>>(dir, wt, li, M, logL);
            }
        }
        k_head<<<800, 256>>>(pre_w + blk * 256 * 128, pre_b + blk * 256,
                             mean_w + blk * 256, mean_b + blk,
                             std_w + blk * 256, std_b + blk,
                             eps + blk * 800, out, blk);
    }
}

// round 17
// speedup vs baseline: 1.1989x; 1.1989x over previous
#include <cuda_runtime.h>
#include <cuda_fp16.h>
#include <math.h>
#include <stdint.h>

#define SQC 0.70710678118f

// ---------------- device scratch ----------------
__device__ float g_prev[1312];
__device__ float g_cond[48000];
__device__ float g_ciAll[4 * 9 * 2 * 800 * 128];
__device__ float g_bp[4 * 8 * 384];
__device__ __half g_WpH[4 * 8 * 384 * 256];
__device__ __half g_WpL[4 * 8 * 384 * 256];
__device__ __half g_hA[800 * 256 * 128];
__device__ __half g_hB[800 * 256 * 128];

// ---------------- helpers ----------------
__device__ __forceinline__ uint32_t smem_u32(const void* p) {
    uint32_t a;
    asm("{ .reg .u64 t; cvta.to.shared.u64 t, %1; cvt.u32.u64 %0, t; }" : "=r"(a) : "l"(p));
    return a;
}
__device__ __forceinline__ void cpa16(uint32_t dst, const void* src) {
    asm volatile("cp.async.cg.shared.global [%0], [%1], 16;"
                 :: "r"(dst), "l"((unsigned long long)__cvta_generic_to_global(src)));
}
__device__ __forceinline__ void mma_f16(float* c, const uint32_t* a, const uint32_t* b) {
    asm volatile("mma.sync.aligned.m16n8k16.row.col.f32.f16.f16.f32 "
                 "{%0,%1,%2,%3}, {%4,%5,%6,%7}, {%8,%9}, {%0,%1,%2,%3};"
                 : "+f"(c[0]), "+f"(c[1]), "+f"(c[2]), "+f"(c[3])
                 : "r"(a[0]), "r"(a[1]), "r"(a[2]), "r"(a[3]), "r"(b[0]), "r"(b[1]));
}
#define LDM4(r0, r1, r2, r3, addr) \
    asm volatile("ldmatrix.sync.aligned.m8n8.x4.shared.b16 {%0,%1,%2,%3}, [%4];" \
                 : "=r"(r0), "=r"(r1), "=r"(r2), "=r"(r3) : "r"(addr))
#define LDM2(r0, r1, addr) \
    asm volatile("ldmatrix.sync.aligned.m8n8.x2.shared.b16 {%0,%1}, [%2];" \
                 : "=r"(r0), "=r"(r1) : "r"(addr))

__device__ __forceinline__ float fsig(float x) { return __fdividef(1.f, 1.f + __expf(-x)); }
__device__ __forceinline__ float fth(float x)  { return 2.f * fsig(2.f * x) - 1.f; }

// ---------------- prep 0: init + cond ----------------
__global__ void k_prep0(const float* __restrict__ sig, float* __restrict__ out,
                        const float* __restrict__ mgc, const float* __restrict__ cw,
                        const float* __restrict__ cb) {
    int b = blockIdx.x, tid = threadIdx.x;
    if (b == 188) {
        for (int i = tid; i < 1312; i += 256) g_prev[i] = sig[i];
        for (int i = tid; i < 800; i += 256) out[i] = sig[512 + i];
        return;
    }
    int id = b * 256 + tid;
    if (id >= 48000) return;
    int t = id / 12000, w = id % 12000;
    const float* wr = cw + w * 60;
    const float* mg = mgc + t * 60;
    float s = cb[w];
#pragma unroll
    for (int k = 0; k < 60; k++) s += mg[k] * wr[k];
    g_cond[(t * 200 + w / 60) * 60 + (w % 60)] = tanhf(s);
}

// ---------------- prep 1: ciall + wprep (fused) ----------------
__global__ void k_prep1(const float* __restrict__ clw, const float* __restrict__ clb,
                        const float* __restrict__ wL, const float* __restrict__ bL) {
    int b = blockIdx.x, tid = threadIdx.x;
    if (b < 1800) {
        __shared__ float cs[32][60];
        int wg = b / 25, nt = b % 25;
        for (int i = tid; i < 32 * 60; i += 256)
            cs[i / 60][i % 60] = g_cond[(nt * 32 + i / 60) * 60 + (i % 60)];
        __syncthreads();
        int f = tid & 127, nh = tid >> 7;
        float wr[60];
        const float* wsrc = clw + (wg * 128 + f) * 60;
#pragma unroll
        for (int k = 0; k < 60; k++) wr[k] = wsrc[k];
        float bia = clb[wg * 128 + f];
        for (int nn = nh * 16; nn < nh * 16 + 16; nn++) {
            float s = bia;
#pragma unroll
            for (int k = 0; k < 60; k++) s += wr[k] * cs[nn][k];
            g_ciAll[(wg * 800 + nt * 32 + nn) * 128 + f] = s;
        }
        return;
    }
    int idx = (b - 1800) * 256 + tid;
    const int total = 4 * 8 * 384 * 256;
    if (idx < total) {
        int k  = idx & 255;
        int r  = (idx >> 8) % 384;
        int bl = idx / (384 * 256);
        int f = r / 3, t = r % 3, kk = k >> 7, c = k & 127;
        float w = wL[(((bl * 3 + t) * 128 + f) * 128 + c) * 2 + kk];
        __half hi = __float2half_rn(w);
        g_WpH[idx] = hi;
        g_WpL[idx] = __float2half_rn(w - __half2float(hi));
    }
    if (idx < 4 * 8 * 384) {
        int r = idx % 384, bl = idx / 384;
        g_bp[idx] = bL[(bl * 3 + (r % 3)) * 128 + (r / 3)];
    }
}

// ---------------- layer 0 (Cin=1), half2 stores (R15 version) ----------------
__global__ void k_layer0(const float* __restrict__ w0, const float* __restrict__ b0, int blk) {
    int gid = blockIdx.x * 256 + threadIdx.x;
    if (gid >= 800 * 256 * 64) return;
    int m = gid >> 6, f2 = gid & 63;
    int n = m >> 8, j = m & 255;
    const float* ci = g_ciAll + (size_t)(blk * 9 * 2) * 102400;
    const float* cg = ci + 102400;
    float a = g_prev[n + 2 * j], b = g_prev[n + 2 * j + 1];
    float x2[2];
#pragma unroll
    for (int p = 0; p < 2; p++) {
        int f = f2 * 2 + p;
        float o0 = a * w0[f * 2]         + b * w0[f * 2 + 1]         + b0[f];
        float o1 = a * w0[(128 + f) * 2] + b * w0[(128 + f) * 2 + 1] + b0[128 + f];
        float o2 = a * w0[(256 + f) * 2] + b * w0[(256 + f) * 2 + 1] + b0[256 + f];
        float it = fth(o0 + ci[n * 128 + f]);
        float gt = fsig(o1 + cg[n * 128 + f]);
        x2[p] = (it * gt + o2) * SQC;
    }
    *((__half2*)g_hA + gid) = __floats2half2_rn(x2[0], x2[1]);
}

// ------------- 1-term layers: BK=64, 4 chunks, 2-slot ring -------
#define B64_BSTG (192 * 144)        /* 27648 */

template<int MI>
__global__ void __launch_bounds__(256, 2)
k_layer_b64(int dir, int wtile, int lidx, int M, int logL) {
    constexpr int BM = 16 * MI;
    constexpr int ASZ = BM * 528;
    constexpr int CPITCH = 200;
    extern __shared__ __align__(16) char sm[];
    float* Cs = (float*)sm;
    uint32_t smb = smem_u32(sm);

    const int tid  = threadIdx.x;
    const int lane = tid & 31, wid = tid >> 5;
    const int gid  = lane >> 2, tig = lane & 3;

    const int m0 = blockIdx.x * BM;
    const int ntile = blockIdx.y;
    const long r0 = (long)wtile * 384 + ntile * 192;

    const __half* A = dir ? g_hB : g_hA;
    __half* O       = dir ? g_hA : g_hB;

    float acc[MI][3][4];
#pragma unroll
    for (int a = 0; a < MI; a++)
#pragma unroll
        for (int b = 0; b < 3; b++)
#pragma unroll
            for (int c = 0; c < 4; c++) acc[a][b][c] = 0.f;

    const __half* srcB = g_WpH + (r0 + wid * 24 + (lane >> 3)) * 256 + (lane & 7) * 8;
    const uint32_t dstB = smb + ASZ + (wid * 24 + (lane >> 3)) * 144 + (lane & 7) * 16;

#pragma unroll
    for (int i = 0; i < 2 * MI; i++) {
        int idx = tid + i * 256;
        int row = idx >> 5, seg = idx & 31;
        cpa16(smb + row * 528 + seg * 16,
              A + (size_t)(m0 + row) * 256 + seg * 8);
    }
    asm volatile("cp.async.commit_group;");

#pragma unroll
    for (int c = 0; c < 2; c++) {
#pragma unroll
        for (int i = 0; i < 6; i++)
            cpa16(dstB + c * B64_BSTG + i * 576, srcB + i * 1024 + c * 64);
        asm volatile("cp.async.commit_group;");
    }

    asm volatile("cp.async.wait_group 2;");
    __syncthreads();

    const int aRow = lane & 15;
    const int aHalf = (lane >> 4) * 16;
    const uint32_t bAdr  = smb + ASZ + (wid * 24 + ((lane >> 4) << 3) + (lane & 7)) * 144
                         + ((lane >> 3) & 1) * 16;
    const uint32_t bAdr2 = smb + ASZ + (wid * 24 + 16 + (lane & 7)) * 144
                         + ((lane >> 3) & 1) * 16;

    for (int ks = 0; ks < 4; ks++) {
        if (ks < 3) asm volatile("cp.async.wait_group 1;");
        else        asm volatile("cp.async.wait_group 0;");
        uint32_t Bst = (ks & 1) * B64_BSTG;

        uint32_t bf[4][3][2];
#pragma unroll
        for (int kf = 0; kf < 4; kf++) {
            LDM4(bf[kf][0][0], bf[kf][0][1], bf[kf][1][0], bf[kf][1][1],
                 bAdr + Bst + kf * 32);
            LDM2(bf[kf][2][0], bf[kf][2][1], bAdr2 + Bst + kf * 32);
        }

        if (ks < 2) {
            int c = ks + 2;
            uint32_t db = dstB + (ks & 1) * B64_BSTG;
#pragma unroll
            for (int i = 0; i < 6; i++)
                cpa16(db + i * 576, srcB + i * 1024 + c * 64);
            asm volatile("cp.async.commit_group;");
        }

#pragma unroll
        for (int kf = 0; kf < 4; kf++) {
            uint32_t af[MI][4];
#pragma unroll
            for (int mi = 0; mi < MI; mi++)
                LDM4(af[mi][0], af[mi][1], af[mi][2], af[mi][3],
                     smb + (mi * 16 + aRow) * 528 + ks * 128 + kf * 32 + aHalf);
#pragma unroll
            for (int mi = 0; mi < MI; mi++)
#pragma unroll
                for (int ni = 0; ni < 3; ni++)
                    mma_f16(acc[mi][ni], af[mi], bf[kf][ni]);
        }
    }
    __syncthreads();

#pragma unroll
    for (int mi = 0; mi < MI; mi++)
#pragma unroll
        for (int ni = 0; ni < 3; ni++) {
            int ml = mi * 16 + gid;
            int rl = wid * 24 + ni * 8 + tig * 2;
            Cs[ml * CPITCH + rl]           = acc[mi][ni][0];
            Cs[ml * CPITCH + rl + 1]       = acc[mi][ni][1];
            Cs[(ml + 8) * CPITCH + rl]     = acc[mi][ni][2];
            Cs[(ml + 8) * CPITCH + rl + 1] = acc[mi][ni][3];
        }
    __syncthreads();

    const int fl = tid & 63;
    const int fg = ntile * 64 + fl;
    const float* bpp = g_bp + wtile * 384 + ntile * 192;
    float b0 = bpp[fl * 3], b1 = bpp[fl * 3 + 1], b2 = bpp[fl * 3 + 2];
    const float* ci = g_ciAll + (size_t)lidx * 2 * 102400;
    const float* cg = ci + 102400;
#pragma unroll
    for (int i = 0; i < BM / 4; i++) {
        int ml = (tid >> 6) + i * 4;
        int m = m0 + ml;
        if (m < M) {
            int n = m >> logL;
            float o0 = Cs[ml * CPITCH + fl * 3]     + b0 + ci[(size_t)n * 128 + fg];
            float o1 = Cs[ml * CPITCH + fl * 3 + 1] + b1 + cg[(size_t)n * 128 + fg];
            float o2 = Cs[ml * CPITCH + fl * 3 + 2] + b2;
            float x = (fth(o0) * fsig(o1) + o2) * SQC;
            O[(size_t)m * 128 + fg] = __float2half_rn(x);
        }
    }
}

// ------------- small layers: BK=32, 2-buffer, TERMS templated ----
template<int MI, int TERMS>
__global__ void __launch_bounds__(256, 2)
k_layer_f(int dir, int wtile, int lidx, int M, int logL) {
    constexpr int BM = 16 * MI;
    constexpr int ASZ = BM * 528;
    constexpr int BROW = 192 * TERMS;
    constexpr int BSTG = BROW * 80;
    constexpr int NR = 3 * TERMS;
    constexpr int CPITCH = 200;

    extern __shared__ __align__(16) char sm[];
    float* Cs = (float*)sm;
    uint32_t smb = smem_u32(sm);

    const int tid  = threadIdx.x;
    const int lane = tid & 31, wid = tid >> 5;
    const int gid  = lane >> 2, tig = lane & 3;

    const int m0 = blockIdx.x * BM;
    const int ntile = blockIdx.y;
    const long r0 = (long)wtile * 384 + ntile * 192;

    const __half* A = dir ? g_hB : g_hA;
    __half* O       = dir ? g_hA : g_hB;

    float acc[MI][3][4];
#pragma unroll
    for (int a = 0; a < MI; a++)
#pragma unroll
        for (int b = 0; b < 3; b++)
#pragma unroll
            for (int c = 0; c < 4; c++) acc[a][b][c] = 0.f;

    const __half* srcp[NR];
    uint32_t dsto[NR];
#pragma unroll
    for (int i = 0; i < NR; i++) {
        int idx = lane + i * 32;
        int rl = idx >> 2, seg = idx & 3;
        int prec = (TERMS == 2) ? (rl >= 24) : 0;
        int gl = rl - prec * 24;
        srcp[i] = (prec ? g_WpL : g_WpH) + (r0 + wid * 24 + gl) * 256 + seg * 8;
        dsto[i] = (uint32_t)((prec * 192 + wid * 24 + gl) * 80 + seg * 16);
    }

#pragma unroll
    for (int i = 0; i < BM * 32 / 256; i++) {
        int idx = tid + i * 256;
        int row = idx >> 5, seg = idx & 31;
        cpa16(smb + row * 528 + seg * 16,
              A + (size_t)(m0 + row) * 256 + seg * 8);
    }
    asm volatile("cp.async.commit_group;");

#pragma unroll
    for (int c = 0; c < 2; c++) {
#pragma unroll
        for (int i = 0; i < NR; i++)
            cpa16(smb + ASZ + c * BSTG + dsto[i], srcp[i] + c * 32);
        asm volatile("cp.async.commit_group;");
    }

    asm volatile("cp.async.wait_group 2;");
    __syncthreads();

    const int aRow = lane & 15;
    const int aHalf = (lane >> 4) * 16;
    const int bRow = wid * 24 + ((lane >> 4) << 3) + (lane & 7);
    const int bRow2 = wid * 24 + 16 + (lane & 7);
    const int bByt = ((lane >> 3) & 1) * 16;

    for (int ks = 0; ks < 8; ks++) {
        if (ks < 7) asm volatile("cp.async.wait_group 1;");
        else        asm volatile("cp.async.wait_group 0;");
        uint32_t Bst = smb + ASZ + (ks & 1) * BSTG;
#pragma unroll
        for (int kf = 0; kf < 2; kf++) {
            uint32_t af[MI][4];
#pragma unroll
            for (int mi = 0; mi < MI; mi++)
                LDM4(af[mi][0], af[mi][1], af[mi][2], af[mi][3],
                     smb + (mi * 16 + aRow) * 528 + ks * 64 + kf * 32 + aHalf);
            uint32_t bf[TERMS][3][2];
#pragma unroll
            for (int prec = 0; prec < TERMS; prec++) {
                LDM4(bf[prec][0][0], bf[prec][0][1], bf[prec][1][0], bf[prec][1][1],
                     Bst + (prec * 192 + bRow) * 80 + bByt + kf * 32);
                LDM2(bf[prec][2][0], bf[prec][2][1],
                     Bst + (prec * 192 + bRow2) * 80 + bByt + kf * 32);
            }
#pragma unroll
            for (int mi = 0; mi < MI; mi++)
#pragma unroll
                for (int ni = 0; ni < 3; ni++) {
#pragma unroll
                    for (int prec = 0; prec < TERMS; prec++)
                        mma_f16(acc[mi][ni], af[mi], bf[prec][ni]);
                }
        }
        if (ks < 6) {
            uint32_t dbase = smb + ASZ + (ks & 1) * BSTG;
#pragma unroll
            for (int i = 0; i < NR; i++)
                cpa16(dbase + dsto[i], srcp[i] + (ks + 2) * 32);
            asm volatile("cp.async.commit_group;");
        }
    }
    __syncthreads();

#pragma unroll
    for (int mi = 0; mi < MI; mi++)
#pragma unroll
        for (int ni = 0; ni < 3; ni++) {
            int ml = mi * 16 + gid;
            int rl = wid * 24 + ni * 8 + tig * 2;
            Cs[ml * CPITCH + rl]           = acc[mi][ni][0];
            Cs[ml * CPITCH + rl + 1]       = acc[mi][ni][1];
            Cs[(ml + 8) * CPITCH + rl]     = acc[mi][ni][2];
            Cs[(ml + 8) * CPITCH + rl + 1] = acc[mi][ni][3];
        }
    __syncthreads();

    const int fl = tid & 63;
    const int fg = ntile * 64 + fl;
    const float* bpp = g_bp + wtile * 384 + ntile * 192;
    float b0 = bpp[fl * 3], b1 = bpp[fl * 3 + 1], b2 = bpp[fl * 3 + 2];
    const float* ci = g_ciAll + (size_t)lidx * 2 * 102400;
    const float* cg = ci + 102400;
#pragma unroll
    for (int i = 0; i < BM / 4; i++) {
        int ml = (tid >> 6) + i * 4;
        int m = m0 + ml;
        if (m < M) {
            int n = m >> logL;
            float o0 = Cs[ml * CPITCH + fl * 3]     + b0 + ci[(size_t)n * 128 + fg];
            float o1 = Cs[ml * CPITCH + fl * 3 + 1] + b1 + cg[(size_t)n * 128 + fg];
            float o2 = Cs[ml * CPITCH + fl * 3 + 2] + b2;
            float x = (fth(o0) * fsig(o1) + o2) * SQC;
            O[(size_t)m * 128 + fg] = __float2half_rn(x);
        }
    }
}

// ---------------- heads ----------------
__global__ void k_head(const float* __restrict__ pw, const float* __restrict__ pb,
                       const float* __restrict__ mw, const float* __restrict__ mb,
                       const float* __restrict__ sw, const float* __restrict__ sb,
                       const float* __restrict__ eps, float* __restrict__ out, int blk) {
    __shared__ float sm_[256], ss_[256];
    int n = blockIdx.x, o = threadIdx.x;
    const __half* h = g_hA + n * 128;
    const float* w = pw + o * 128;
    float s = pb[o];
#pragma unroll
    for (int k = 0; k < 128; k++) s += __half2float(h[k]) * w[k];
    s = fmaxf(s, 0.f);
    sm_[o] = s * mw[o];
    ss_[o] = s * sw[o];
    __syncthreads();
    for (int st = 128; st > 0; st >>= 1) {
        if (o < st) { sm_[o] += sm_[o + st]; ss_[o] += ss_[o + st]; }
        __syncthreads();
    }
    if (o == 0) {
        float mean = sm_[0] + mb[0];
        float logv = ss_[0] + sb[0];
        float nx = eps[n] * expf(0.5f * logv) + mean;
        out[800 + n]  = mean;
        out[1600 + n] = logv;
        if (n >= 288) out[2400 + blk * 512 + (n - 288)] = nx;
        g_prev[512 + n] = nx;
    }
}

// ---------------- launcher ----------------
extern "C" void kernel_launch(void* const* d_in, const int* in_sizes, int n_in,
                              void* d_out, int out_size) {
    const float* mgc       = (const float*)d_in[0];
    const float* signal    = (const float*)d_in[1];
    const float* cond_w    = (const float*)d_in[2];
    const float* cond_b    = (const float*)d_in[3];
    const float* conv0_w   = (const float*)d_in[4];
    const float* conv0_b   = (const float*)d_in[5];
    const float* convL_w   = (const float*)d_in[6];
    const float* convL_b   = (const float*)d_in[7];
    const float* condlin_w = (const float*)d_in[8];
    const float* condlin_b = (const float*)d_in[9];
    const float* pre_w     = (const float*)d_in[10];
    const float* pre_b     = (const float*)d_in[11];
    const float* mean_w    = (const float*)d_in[12];
    const float* mean_b    = (const float*)d_in[13];
    const float* std_w     = (const float*)d_in[14];
    const float* std_b     = (const float*)d_in[15];
    const float* eps       = (const float*)d_in[16];
    float* out = (float*)d_out;

    const int SMB4 = 64 * 528 + 2 * B64_BSTG;   // 89088
    const int SMB2 = 32 * 528 + 2 * B64_BSTG;   // 72192
    const int SM11 = 16 * 528 + 2 * 192 * 80;   // 39168
    const int SM12 = 16 * 528 + 2 * 384 * 80;   // 69888

    static bool attrSet = false;
    if (!attrSet) {
        cudaFuncSetAttribute((const void*)k_layer_b64<4>, cudaFuncAttributeMaxDynamicSharedMemorySize, SMB4);
        cudaFuncSetAttribute((const void*)k_layer_b64<2>, cudaFuncAttributeMaxDynamicSharedMemorySize, SMB2);
        cudaFuncSetAttribute((const void*)k_layer_f<1, 1>, cudaFuncAttributeMaxDynamicSharedMemorySize, SM11);
        cudaFuncSetAttribute((const void*)k_layer_f<1, 2>, cudaFuncAttributeMaxDynamicSharedMemorySize, SM12);
        attrSet = true;
    }

    k_prep0<<<189, 256>>>(signal, out, mgc, cond_w, cond_b);
    k_prep1<<<1800 + 12288, 256>>>(condlin_w, condlin_b, convL_w, convL_b);

    for (int blk = 0; blk < 4; blk++) {
        k_layer0<<<51200, 256>>>(conv0_w + blk * 768, conv0_b + blk * 384, blk);
        for (int l = 1; l <= 8; l++) {
            int logL = 8 - l;
            int M = 800 << logL;
            int dir = (l & 1) ? 0 : 1;
            int wt = blk * 8 + l - 1, li = blk * 9 + l;
            if (M >= 6400) {
                k_layer_b64<4><<<dim3(M / 64, 2), 256, SMB4>>>(dir, wt, li, M, logL);
            } else if (M >= 3200) {
                k_layer_b64<2><<<dim3(M / 32, 2), 256, SMB2>>>(dir, wt, li, M, logL);
            } else if (M >= 1600) {
                k_layer_f<1, 1><<<dim3(M / 16, 2), 256, SM11>>>(dir, wt, li, M, logL);
            } else {
                k_layer_f<1, 2><<<dim3(M / 16, 2), 256, SM12>>>(dir, wt, li, M, logL);
            }
        }
        k_head<<<800, 256>>>(pre_w + blk * 256 * 128, pre_b + blk * 256,
                             mean_w + blk * 256, mean_b + blk,
                             std_w + blk * 256, std_b + blk,
                             eps + blk * 800, out, blk);
    }
}